// round 5
// baseline (speedup 1.0000x reference)
#include <cuda_runtime.h>
#include <cuda_bf16.h>
#include <math.h>

#define BB 64
#define TT 4096
#define FF 64
#define DHH 64
#define DGG 128
#define G3 384   // 3*DG
#define WCTAS 84 // worker (encoder->head) CTAs

typedef unsigned long long u64;

// ---------------- scratch (device globals; no cudaMalloc allowed) ----------------
// gx stored TRANSPOSED: [b][h][t]
__device__ __align__(128) float g_gx_buf[(size_t)BB * G3 * TT];   // 402.7 MB
__device__ __align__(128) float g_z_buf[(size_t)BB * TT * DGG];   // 134.2 MB
__device__ __align__(128) unsigned char g_mask[(size_t)BB * TT * FF]; // 16.7 MB canonical
__device__ double g_sum[FF];
__device__ double g_sumsq[FF];
__device__ double g_mcnt;
__device__ double g_loss;
__device__ int g_flag_byte;
__device__ int g_flag_half;
__device__ int g_prog[BB];          // GRU progress per batch (t rows published)
__device__ int g_tiledone[64 * 64]; // encoder tile flags: [tb][b]
__device__ int g_statsctr;
__device__ int g_headctr;

// ---------------- helpers ----------------
__device__ __forceinline__ u64 pk2(float lo, float hi) {
    u64 r; asm("mov.b64 %0, {%1, %2};" : "=l"(r) : "f"(lo), "f"(hi)); return r;
}
__device__ __forceinline__ float2 upk2(u64 v) {
    float2 r; asm("mov.b64 {%0, %1}, %2;" : "=f"(r.x), "=f"(r.y) : "l"(v)); return r;
}
__device__ __forceinline__ u64 fma2(u64 a, u64 b, u64 c) {
    u64 d; asm("fma.rn.f32x2 %0, %1, %2, %3;" : "=l"(d) : "l"(a), "l"(b), "l"(c)); return d;
}
__device__ __forceinline__ float gelu_exact(float a) {
    return 0.5f * a * (1.0f + erff(a * 0.70710678118654752440f));
}
__device__ __forceinline__ float sigm(float x) {
    return __fdividef(1.0f, 1.0f + __expf(-x));
}
__device__ __forceinline__ float tanh_fast(float x) {
    float s = copysignf(1.0f, x);
    float e = __expf(-2.0f * fabsf(x));
    return s * __fdividef(1.0f - e, 1.0f + e);
}
__device__ __forceinline__ int ld_acq(const int* p) {
    int v; asm volatile("ld.global.acquire.gpu.b32 %0, [%1];" : "=r"(v) : "l"(p) : "memory");
    return v;
}
__device__ __forceinline__ void st_rel(int* p, int v) {
    asm volatile("st.global.release.gpu.b32 [%0], %1;" :: "l"(p), "r"(v) : "memory");
}
__device__ __forceinline__ void spin_ge(const int* p, int target) {
    long long t0 = clock64();
    while (ld_acq(p) < target) {
        __nanosleep(128);
        if (clock64() - t0 > 20000000000LL) break;  // safety valve
    }
}

// ---------------- K0a: reset scalars ----------------
__global__ void k_init() {
    int t = threadIdx.x;
    if (t < FF) { g_sum[t] = 0.0; g_sumsq[t] = 0.0; }
    if (t == FF)     g_mcnt = 0.0;
    if (t == FF + 1) g_loss = 0.0;
    if (t == FF + 2) g_flag_byte = 0;
    if (t == FF + 3) g_flag_half = 0;
    if (t == FF + 4) g_statsctr = 0;
    if (t == FF + 5) g_headctr = 0;
}

// ---------------- K0b: reset flag arrays ----------------
__global__ void k_init2() {
    int i = blockIdx.x * blockDim.x + threadIdx.x;
    if (i < 64 * 64) g_tiledone[i] = 0;
    if (i < BB) g_prog[i] = 0;
}

// ---------------- K1: probe mask element width from bit patterns ----------------
__global__ __launch_bounds__(256) void k_probe(const unsigned int* __restrict__ m) {
    int byteF = 0, halfF = 0;
    size_t nwords = (size_t)BB * TT * FF / 4;
    for (size_t i = (size_t)blockIdx.x * blockDim.x + threadIdx.x; i < nwords;
         i += (size_t)gridDim.x * blockDim.x) {
        unsigned v = m[i];
        if (v == 0u || v == 1u || v == 0x3F800000u) continue;
        bool b01 = true;
        #pragma unroll
        for (int k = 0; k < 4; k++) {
            unsigned bt = (v >> (8 * k)) & 0xFFu;
            if (bt > 1u) b01 = false;
        }
        if (b01) { byteF = 1; continue; }
        bool h16 = true;
        #pragma unroll
        for (int k = 0; k < 2; k++) {
            unsigned h = (v >> (16 * k)) & 0xFFFFu;
            if (h != 0u && h != 0x3F80u) h16 = false;
        }
        if (h16) { halfF = 1; continue; }
        byteF = 1;
    }
    if (byteF) g_flag_byte = 1;
    if (halfF) g_flag_half = 1;
}

// ---------------- encoder smem layout (floats) ----------------
#define E_W1   0        // 64x64  stem_w [f][d]
#define E_CW   4096     // 192x64 conv_w transposed [(i*3+k)][o]
#define E_WIH  16384    // 64x384 w_ih transposed [d][h]
#define E_SB   40960
#define E_CB   41024
#define E_BIH  41088
#define E_X    41472    // 66x64
#define E_H0   45696    // 66x64
#define E_H1   49920    // 64x65
#define E_TOT  54080    // floats -> 216320 bytes

// ---------------- head smem layout (floats) ----------------
#define H_W1   0        // 128x128 [k][o]
#define H_W2   16384
#define H_W3   32768
#define H_B1   40960
#define H_B2   41088
#define H_B3   41216
#define H_INV  41280
#define H_ZB   41344    // 128x34
#define H_RB   45696    // 128x34
#define H_TOT  50048    // floats; sred (256 dbl) + tile slot follow

#define SMEM_BYTES (E_TOT * 4)

// ---------------- GRU step: double-buffered h, named-barrier mid sync ----------------
__device__ __forceinline__ void gru_step2(
    int j, int bar_id, float gxv, const u64* __restrict__ w, float bj,
    const float* shR, float* shW, float* sA, float* sGn, float* zrow)
{
    __syncthreads();                      // h (shR) complete, sA free for rewrite
    u64 acc0 = pk2(bj, 0.f);
    u64 acc1 = pk2(0.f, 0.f);
    const ulonglong2* hp = (const ulonglong2*)shR;
    #pragma unroll
    for (int i = 0; i < 32; i++) {
        ulonglong2 hv = hp[i];            // broadcast LDS.128
        acc0 = fma2(hv.x, w[2 * i], acc0);
        acc1 = fma2(hv.y, w[2 * i + 1], acc1);
    }
    float2 s0 = upk2(acc0), s1 = upk2(acc1);
    float gh = (s0.x + s0.y) + (s1.x + s1.y);
    if (j < 256) {
        sA[j] = gh + gxv;
    } else {
        sA[j] = gh;
        sGn[j - 256] = gxv;
    }
    // sync only the 3-warp producer group {w, w+4, w+8} for this gate warp
    asm volatile("bar.sync %0, 96;" :: "r"(bar_id) : "memory");
    if (j < DGG) {
        float r = sigm(sA[j]);
        float z = sigm(sA[j + 128]);
        float n = tanh_fast(sGn[j] + r * sA[j + 256]);
        float hn = (1.f - z) * n + z * shR[j];
        shW[j] = hn;                      // write OTHER buffer: laggard readers of shR safe
        zrow[j] = hn;
    }
}

// ---------------- K2: ONE persistent kernel: stats + encoder + GRU + head ----------------
__global__ __launch_bounds__(384, 1) void k_gruhead(
    const float* __restrict__ x, const void* __restrict__ fm,
    const float* __restrict__ stem_w, const float* __restrict__ stem_b,
    const float* __restrict__ conv_w, const float* __restrict__ conv_b,
    const float* __restrict__ w_ih, const float* __restrict__ b_ih,
    const float* __restrict__ whh, const float* __restrict__ bhh,
    const float* __restrict__ h1_w, const float* __restrict__ h1_b,
    const float* __restrict__ h2_w, const float* __restrict__ h2_b,
    const float* __restrict__ h3_w, const float* __restrict__ h3_b)
{
    extern __shared__ float smem[];
    int tid = threadIdx.x;
    const unsigned char* m8  = (const unsigned char*)fm;
    const unsigned short* m16 = (const unsigned short*)fm;
    const unsigned int* m32  = (const unsigned int*)fm;
    int bF = g_flag_byte, hF = g_flag_half;

    if (blockIdx.x < BB) {
        // ======================= GRU role (CTA b) =======================
        int b = blockIdx.x;

        // ---- stats partial on slice b, fp32 folded to double every 16 rows ----
        {
            int f4 = (tid & 15) * 4;
            int rg = tid >> 4;      // 0..23
            double ds0 = 0, ds1 = 0, ds2 = 0, ds3 = 0;
            double dq0 = 0, dq1 = 0, dq2 = 0, dq3 = 0;
            float4 s = make_float4(0.f, 0.f, 0.f, 0.f);
            float4 q = make_float4(0.f, 0.f, 0.f, 0.f);
            int mc = 0, c16 = 0;
            for (int r = b * 4096 + rg; r < (b + 1) * 4096; r += 24) {
                size_t gi = (size_t)r * FF + f4;
                float4 v = *(const float4*)(x + gi);
                int m0, m1, m2, m3;
                if (bF) {
                    unsigned w_ = *(const unsigned*)(m8 + gi);
                    m0 = (w_ & 0xFFu) != 0; m1 = ((w_ >> 8) & 0xFFu) != 0;
                    m2 = ((w_ >> 16) & 0xFFu) != 0; m3 = (w_ >> 24) != 0;
                } else if (hF) {
                    uint2 w_ = *(const uint2*)(m16 + gi);
                    m0 = (w_.x & 0xFFFFu) != 0; m1 = (w_.x >> 16) != 0;
                    m2 = (w_.y & 0xFFFFu) != 0; m3 = (w_.y >> 16) != 0;
                } else {
                    uint4 w_ = *(const uint4*)(m32 + gi);
                    m0 = w_.x != 0; m1 = w_.y != 0; m2 = w_.z != 0; m3 = w_.w != 0;
                }
                s.x += v.x; s.y += v.y; s.z += v.z; s.w += v.w;
                q.x = fmaf(v.x, v.x, q.x); q.y = fmaf(v.y, v.y, q.y);
                q.z = fmaf(v.z, v.z, q.z); q.w = fmaf(v.w, v.w, q.w);
                mc += m0 + m1 + m2 + m3;
                if (++c16 == 16) {
                    ds0 += s.x; ds1 += s.y; ds2 += s.z; ds3 += s.w;
                    dq0 += q.x; dq1 += q.y; dq2 += q.z; dq3 += q.w;
                    s = make_float4(0.f, 0.f, 0.f, 0.f);
                    q = make_float4(0.f, 0.f, 0.f, 0.f);
                    c16 = 0;
                }
            }
            ds0 += s.x; ds1 += s.y; ds2 += s.z; ds3 += s.w;
            dq0 += q.x; dq1 += q.y; dq2 += q.z; dq3 += q.w;

            double* dss = (double*)smem;              // 24*64 doubles
            double* dsq = dss + 1536;                 // 24*64 doubles
            int* sm_ = (int*)(dsq + 1536);            // 384 ints
            dss[rg * 64 + f4] = ds0; dss[rg * 64 + f4 + 1] = ds1;
            dss[rg * 64 + f4 + 2] = ds2; dss[rg * 64 + f4 + 3] = ds3;
            dsq[rg * 64 + f4] = dq0; dsq[rg * 64 + f4 + 1] = dq1;
            dsq[rg * 64 + f4 + 2] = dq2; dsq[rg * 64 + f4 + 3] = dq3;
            sm_[tid] = mc;
            __syncthreads();
            if (tid < 64) {
                double S = 0.0, Q = 0.0;
                #pragma unroll
                for (int g = 0; g < 24; g++) { S += dss[g * 64 + tid]; Q += dsq[g * 64 + tid]; }
                atomicAdd(&g_sum[tid], S);
                atomicAdd(&g_sumsq[tid], Q);
            }
            __syncthreads();
            if (tid == 0) {
                int tot = 0;
                for (int i = 0; i < 384; i++) tot += sm_[i];
                atomicAdd(&g_mcnt, (double)tot);
                __threadfence();
                atomicAdd(&g_statsctr, 1);
            }
            __syncthreads();   // smem free for GRU reuse
        }

        // ---- GRU recurrence (double-buffered h) ----
        float* sh0 = smem;            // 128
        float* sh1 = smem + 128;      // 128
        float* sA  = smem + 256;      // 384
        float* sGn = smem + 640;      // 128
        int j = tid;
        int bar_id = ((j >> 5) & 3) + 1;

        u64 w[64];
        {
            const u64* wp = (const u64*)(whh + (size_t)j * DGG);
            #pragma unroll
            for (int i = 0; i < 64; i++) w[i] = wp[i];
        }
        float bj = bhh[j];
        if (j < DGG) sh0[j] = 0.f;

        const float2* gxp = (const float2*)(g_gx_buf + ((size_t)b * G3 + j) * TT);
        float* zbase = g_z_buf + (size_t)b * TT * DGG;

        if (j == 0) spin_ge(&g_tiledone[0 * 64 + b], 1);   // region 0 ready
        __syncthreads();

        float2 cur = gxp[0];

        for (int tb = 0; tb < TT / 2; tb++) {
            if (j == 0) {
                if ((tb & 31) == 0) {
                    int reg = tb >> 5;                       // region = (2*tb)>>6
                    if (reg + 1 < 64) spin_ge(&g_tiledone[(reg + 1) * 64 + b], 1);
                }
                if ((tb & 15) == 0 && tb > 0) {              // publish every 32 steps
                    __threadfence();
                    st_rel(&g_prog[b], tb * 2);
                }
            }
            float2 nxt = make_float2(0.f, 0.f);
            if (tb + 1 < TT / 2) nxt = gxp[tb + 1];
            int t = tb * 2;

            gru_step2(j, bar_id, cur.x, w, bj, sh0, sh1, sA, sGn, zbase + (size_t)t * DGG);
            gru_step2(j, bar_id, cur.y, w, bj, sh1, sh0, sA, sGn, zbase + (size_t)(t + 1) * DGG);

            cur = nxt;
        }
        __syncthreads();
        if (j == 0) {
            __threadfence();
            st_rel(&g_prog[b], TT);
        }
        return;
    }

    // ======================= worker role: encoder, then head =======================
    int hb = blockIdx.x - BB;       // 0..83
    const int NT = 384;

    // ---- encoder phase ----
    for (int i = tid; i < 4096; i += NT) smem[E_W1 + i] = stem_w[i];
    for (int i = tid; i < 12288; i += NT) {
        int o = i & 63, ik = i >> 6;
        smem[E_CW + i] = conv_w[o * 192 + ik];
    }
    for (int i = tid; i < 24576; i += NT) {
        int h = i % 384, d = i / 384;
        smem[E_WIH + i] = w_ih[h * 64 + d];
    }
    if (tid < 64) { smem[E_SB + tid] = stem_b[tid]; smem[E_CB + tid] = conv_b[tid]; }
    if (tid >= 64 && tid < 448) smem[E_BIH + tid - 64] = b_ih[tid - 64];
    __syncthreads();

    for (int tau = hb; tau < 4096; tau += WCTAS) {
        int b = tau & 63;
        int t0 = (tau >> 6) << 6;        // t-major: all b for each 64-t block first

        // masked X load (raw-width dispatch) + canonical mask writeback (interior rows)
        for (int i = tid; i < 66 * 64; i += NT) {
            int row = i >> 6, f = i & 63;
            int t = t0 - 1 + row;
            float v = 0.f;
            if (t >= 0 && t < TT) {
                size_t gi = ((size_t)b * TT + t) * FF + f;
                unsigned mm;
                if (bF) mm = m8[gi];
                else if (hF) mm = m16[gi];
                else mm = m32[gi];
                v = mm ? 0.f : x[gi];
                if (row >= 1 && row < 65) g_mask[gi] = (unsigned char)(mm ? 1 : 0);
            }
            smem[E_X + i] = v;
        }
        __syncthreads();

        // stem GEMM + GELU (FFMA2); boundary rows zeroed
        for (int q = tid; q < 66 * 16; q += NT) {
            int i = q >> 4, d4 = (q & 15) << 2;
            int t = t0 - 1 + i;
            const u64* bp = (const u64*)&smem[E_SB + d4];
            u64 a0 = bp[0], a1 = bp[1];
            const float* xr = &smem[E_X + i * 64];
            #pragma unroll 16
            for (int f = 0; f < 64; f++) {
                float xv = xr[f];
                u64 x2 = pk2(xv, xv);
                const u64* ww = (const u64*)&smem[E_W1 + f * 64 + d4];
                a0 = fma2(x2, ww[0], a0);
                a1 = fma2(x2, ww[1], a1);
            }
            bool valid = (t >= 0) && (t < TT);
            float2 v0 = upk2(a0), v1 = upk2(a1);
            float4 r;
            r.x = valid ? gelu_exact(v0.x) : 0.f;
            r.y = valid ? gelu_exact(v0.y) : 0.f;
            r.z = valid ? gelu_exact(v1.x) : 0.f;
            r.w = valid ? gelu_exact(v1.y) : 0.f;
            *(float4*)&smem[E_H0 + i * 64 + d4] = r;
        }
        __syncthreads();

        // conv1d k=3 + GELU (FFMA2)
        for (int q = tid; q < 64 * 16; q += NT) {
            int tl = q >> 4, o4 = (q & 15) << 2;
            const u64* bp = (const u64*)&smem[E_CB + o4];
            u64 a0 = bp[0], a1 = bp[1];
            const float* h0a = &smem[E_H0 + tl * 64];
            const float* h0b = h0a + 64;
            const float* h0c = h0a + 128;
            #pragma unroll 8
            for (int i = 0; i < 64; i++) {
                u64 p0 = pk2(h0a[i], h0a[i]);
                u64 p1 = pk2(h0b[i], h0b[i]);
                u64 p2 = pk2(h0c[i], h0c[i]);
                const u64* w0 = (const u64*)&smem[E_CW + (i * 3 + 0) * 64 + o4];
                const u64* w1 = (const u64*)&smem[E_CW + (i * 3 + 1) * 64 + o4];
                const u64* w2 = (const u64*)&smem[E_CW + (i * 3 + 2) * 64 + o4];
                a0 = fma2(p0, w0[0], fma2(p1, w1[0], fma2(p2, w2[0], a0)));
                a1 = fma2(p0, w0[1], fma2(p1, w1[1], fma2(p2, w2[1], a1)));
            }
            float2 v0 = upk2(a0), v1 = upk2(a1);
            float* h1 = &smem[E_H1 + tl * 65 + o4];
            h1[0] = gelu_exact(v0.x);
            h1[1] = gelu_exact(v0.y);
            h1[2] = gelu_exact(v1.x);
            h1[3] = gelu_exact(v1.y);
        }
        __syncthreads();

        // gx GEMM (FFMA2) -> transposed store [b][h][t]
        for (int task = tid; task < 64 * 48; task += NT) {
            int tl = task & 63;
            int h8 = (task >> 6) << 3;
            u64 a0 = *(const u64*)&smem[E_BIH + h8];
            u64 a1 = *(const u64*)&smem[E_BIH + h8 + 2];
            u64 a2 = *(const u64*)&smem[E_BIH + h8 + 4];
            u64 a3 = *(const u64*)&smem[E_BIH + h8 + 6];
            const float* h1p = &smem[E_H1 + tl * 65];
            #pragma unroll 16
            for (int d = 0; d < 64; d++) {
                float hv = h1p[d];
                u64 h2 = pk2(hv, hv);
                const u64* ww = (const u64*)&smem[E_WIH + d * 384 + h8];
                a0 = fma2(h2, ww[0], a0);
                a1 = fma2(h2, ww[1], a1);
                a2 = fma2(h2, ww[2], a2);
                a3 = fma2(h2, ww[3], a3);
            }
            float2 r0 = upk2(a0), r1 = upk2(a1), r2 = upk2(a2), r3 = upk2(a3);
            float* gp = g_gx_buf + ((size_t)b * G3 + h8) * TT + (t0 + tl);
            gp[0]              = r0.x;
            gp[(size_t)TT]     = r0.y;
            gp[(size_t)2 * TT] = r1.x;
            gp[(size_t)3 * TT] = r1.y;
            gp[(size_t)4 * TT] = r2.x;
            gp[(size_t)5 * TT] = r2.y;
            gp[(size_t)6 * TT] = r3.x;
            gp[(size_t)7 * TT] = r3.y;
        }
        __syncthreads();
        if (tid == 0) {
            __threadfence();
            st_rel(&g_tiledone[tau], 1);
        }
    }

    // ---- head phase ----
    __syncthreads();
    if (tid >= 256) return;           // warps 8-11 exit whole

    double* sred = (double*)(smem + H_TOT);          // 256 doubles
    int* tileSlot = (int*)(smem + H_TOT + 512);

    for (int i = tid; i < 16384; i += 256) smem[H_W1 + i] = h1_w[i];
    for (int i = tid; i < 16384; i += 256) smem[H_W2 + i] = h2_w[i];
    for (int i = tid; i < 8192; i += 256) smem[H_W3 + i] = h3_w[i];
    if (tid < 128) { smem[H_B1 + tid] = h1_b[tid]; smem[H_B2 + tid] = h2_b[tid]; }
    if (tid >= 128 && tid < 192) smem[H_B3 + tid - 128] = h3_b[tid - 128];
    if (tid == 0) spin_ge(&g_statsctr, BB);          // all stats partials in
    __syncthreads();
    if (tid < 64) {
        double N = (double)(BB * TT);
        double mean = g_sum[tid] / N;
        double var = (g_sumsq[tid] - N * mean * mean) / (N - 1.0);
        double sd = sqrt(var) + 1e-8;
        smem[H_INV + tid] = (float)(1.0 / (sd * sd));
    }
    __syncthreads();

    float lacc = 0.f;

    while (true) {
        if (tid == 0) *tileSlot = atomicAdd(&g_headctr, 1);
        __syncthreads();
        int tile = *tileSlot;
        __syncthreads();
        if (tile >= BB * (TT / 32)) break;
        int b = tile & 63;
        int t0 = (tile >> 6) << 5;

        if (tid == 0) spin_ge(&g_prog[b], t0 + 32);
        __syncthreads();

        // load z transposed [k][t]
        for (int i = tid; i < 4096; i += 256) {
            int k = i & 127, t = i >> 7;
            smem[H_ZB + k * 34 + t] = g_z_buf[((size_t)b * TT + t0 + t) * DGG + k];
        }
        __syncthreads();

        // layer1
        {
            int o = tid & 127, g = tid >> 7;
            float bo = smem[H_B1 + o];
            u64 A[8];
            #pragma unroll
            for (int p = 0; p < 8; p++) A[p] = pk2(bo, bo);
            #pragma unroll 4
            for (int k = 0; k < 128; k++) {
                float wv = smem[H_W1 + k * 128 + o];
                u64 w2 = pk2(wv, wv);
                const float* zr = &smem[H_ZB + k * 34 + g * 16];
                #pragma unroll
                for (int p = 0; p < 8; p++) A[p] = fma2(*(const u64*)(zr + 2 * p), w2, A[p]);
            }
            float* rr = &smem[H_RB + o * 34 + g * 16];
            #pragma unroll
            for (int p = 0; p < 8; p++) {
                float2 v = upk2(A[p]);
                rr[2 * p]     = gelu_exact(v.x);
                rr[2 * p + 1] = gelu_exact(v.y);
            }
        }
        __syncthreads();

        // layer2
        {
            int o = tid & 127, g = tid >> 7;
            float bo = smem[H_B2 + o];
            u64 A[8];
            #pragma unroll
            for (int p = 0; p < 8; p++) A[p] = pk2(bo, bo);
            #pragma unroll 4
            for (int k = 0; k < 128; k++) {
                float wv = smem[H_W2 + k * 128 + o];
                u64 w2 = pk2(wv, wv);
                const float* zr = &smem[H_RB + k * 34 + g * 16];
                #pragma unroll
                for (int p = 0; p < 8; p++) A[p] = fma2(*(const u64*)(zr + 2 * p), w2, A[p]);
            }
            float* rr = &smem[H_ZB + o * 34 + g * 16];
            #pragma unroll
            for (int p = 0; p < 8; p++) {
                float2 v = upk2(A[p]);
                rr[2 * p]     = gelu_exact(v.x);
                rr[2 * p + 1] = gelu_exact(v.y);
            }
        }
        __syncthreads();

        // layer3 + loss
        {
            int o = tid & 63, g = tid >> 6;
            float bo = smem[H_B3 + o];
            float invs = smem[H_INV + o];
            u64 A[4];
            #pragma unroll
            for (int p = 0; p < 4; p++) A[p] = pk2(bo, bo);
            #pragma unroll 4
            for (int k = 0; k < 128; k++) {
                float wv = smem[H_W3 + k * 64 + o];
                u64 w2 = pk2(wv, wv);
                const float* zr = &smem[H_ZB + k * 34 + g * 8];
                #pragma unroll
                for (int p = 0; p < 4; p++) A[p] = fma2(*(const u64*)(zr + 2 * p), w2, A[p]);
            }
            #pragma unroll
            for (int p = 0; p < 4; p++) {
                int t = t0 + g * 8 + 2 * p;
                size_t gi = ((size_t)b * TT + t) * FF + o;
                float2 v = upk2(A[p]);
                float d0 = v.x - x[gi];
                float d1 = v.y - x[gi + FF];
                if (g_mask[gi])      lacc = fmaf(d0 * d0, invs, lacc);
                if (g_mask[gi + FF]) lacc = fmaf(d1 * d1, invs, lacc);
            }
        }
        __syncthreads();    // ZB readers done before next tile rewrites
    }

    sred[tid] = (double)lacc;
    __syncthreads();
    for (int s = 128; s > 0; s >>= 1) {
        if (tid < s) sred[tid] += sred[tid + s];
        __syncthreads();
    }
    if (tid == 0) atomicAdd(&g_loss, sred[0]);
}

// ---------------- K3: finalize ----------------
__global__ void k_final(float* out) {
    double denom = g_mcnt > 1.0 ? g_mcnt : 1.0;
    out[0] = (float)(g_loss / denom);
}

// ---------------- launch ----------------
extern "C" void kernel_launch(void* const* d_in, const int* in_sizes, int n_in,
                              void* d_out, int out_size) {
    const float* x          = (const float*)d_in[0];
    const void*  fm         = (const void*)d_in[1];
    const float* stem_w     = (const float*)d_in[2];
    const float* stem_b     = (const float*)d_in[3];
    const float* conv_w     = (const float*)d_in[4];
    const float* conv_b     = (const float*)d_in[5];
    const float* gru_w_ih   = (const float*)d_in[6];
    const float* gru_w_hh   = (const float*)d_in[7];
    const float* gru_b_ih   = (const float*)d_in[8];
    const float* gru_b_hh   = (const float*)d_in[9];
    const float* h1_w       = (const float*)d_in[10];
    const float* h1_b       = (const float*)d_in[11];
    const float* h2_w       = (const float*)d_in[12];
    const float* h2_b       = (const float*)d_in[13];
    const float* h3_w       = (const float*)d_in[14];
    const float* h3_b       = (const float*)d_in[15];
    float* out = (float*)d_out;

    cudaFuncSetAttribute(k_gruhead, cudaFuncAttributeMaxDynamicSharedMemorySize, SMEM_BYTES);

    k_init<<<1, 256>>>();
    k_init2<<<8, 512>>>();
    k_probe<<<512, 256>>>((const unsigned int*)fm);
    k_gruhead<<<BB + WCTAS, 384, SMEM_BYTES>>>(
        x, fm, stem_w, stem_b, conv_w, conv_b, gru_w_ih, gru_b_ih,
        gru_w_hh, gru_b_hh, h1_w, h1_b, h2_w, h2_b, h3_w, h3_b);
    k_final<<<1, 1>>>(out);
}